// round 14
// baseline (speedup 1.0000x reference)
#include <cuda_runtime.h>
#include <cuda_fp16.h>
#include <stdint.h>

// Problem constants (fixed by setup_inputs)
#define N0     256000    // nodes
#define FIN    64
#define F1     16        // conv1 out
#define F2     32        // conv2 out
#define NC0    25600     // level-0 clusters (= N0/10)
#define CPG    400       // clusters per graph
#define NB     64        // graphs
#define MD0    40        // max degree, level-0 graph

// fp16 gather tables (+1 zero pad row each); fp32 accumulation everywhere.
__device__ __align__(16) __half g_xp1h[(N0 + 1) * F1];     // x@W1, 8 MB
__device__ __align__(16) __half g_xpoolh[(NC0 + 1) * F1];  // pooled feats, 0.8 MB
__device__ __align__(16) float  g_s2[NC0 * F1];            // conv2 gathered sums (pre-W2)

// Level-0 padded CSR
__device__ int g_cnt0[N0];
__device__ int g_cols0[N0 * MD0];
// Level-1 row bounds (edge_index1 sorted by row -> implicit CSR)
__device__ int g_bnd[2 * NC0];

// ---------------------------------------------------------------------------
// K1: xp1 = x @ W1 (smem-tiled, fp16 out) + init blocks
#define PROJ_BLKS (N0 / 64)   // 4000
__global__ void k_proj1_init(const float* __restrict__ x, const float* __restrict__ W1) {
    if (blockIdx.x >= PROJ_BLKS) {
        int t = (blockIdx.x - PROJ_BLKS) * 256 + threadIdx.x;
        if (t < N0) g_cnt0[t] = 0;
        if (t < 2 * NC0) g_bnd[t] = 0;
        if (t < F1) g_xp1h[N0 * F1 + t] = __float2half(0.f);
        if (t < F1) g_xpoolh[NC0 * F1 + t] = __float2half(0.f);
        return;
    }
    __shared__ float xs[64 * FIN];
    __shared__ float Ws[FIN * F1];
    int base = blockIdx.x * 64;
    const float4* xsrc = reinterpret_cast<const float4*>(x + (size_t)base * FIN);
    float4* xd = reinterpret_cast<float4*>(xs);
    for (int i = threadIdx.x; i < 64 * FIN / 4; i += 256) xd[i] = xsrc[i];
    for (int i = threadIdx.x; i < FIN * F1; i += 256) Ws[i] = W1[i];
    __syncthreads();
    for (int o = threadIdx.x; o < 64 * F1; o += 256) {
        int n = o >> 4, f = o & 15;
        float acc = 0.f;
        const float* xr = xs + n * FIN;
#pragma unroll
        for (int k = 0; k < FIN; k++) acc = fmaf(xr[k], Ws[k * F1 + f], acc);
        g_xp1h[(size_t)(base + n) * F1 + f] = __float2half(acc);
    }
}

// ---------------------------------------------------------------------------
// K2: level-0 padded-CSR fill + level-1 row bounds
__global__ void k_fill_bounds(const int* __restrict__ ei, int E0_,
                              const int* __restrict__ ei1, int E1_) {
    int e = blockIdx.x * blockDim.x + threadIdx.x;
    if (e < E0_) {
        int row = ei[e];
        int col = ei[E0_ + e];
        int pos = atomicAdd(&g_cnt0[row], 1);
        if (pos < MD0) g_cols0[(size_t)row * MD0 + pos] = col;
    }
    if (e < E1_) {
        int r = ei1[e];
        if (e == 0 || ei1[e - 1] != r) g_bnd[r] = e;
        if (e == E1_ - 1 || ei1[e + 1] != r) g_bnd[NC0 + r] = e + 1;
    }
}

// ---------------------------------------------------------------------------
// helper: accumulate 4 fp16 (as uint2) into float4 (fp32 math)
__device__ __forceinline__ void acc_h4(float4& acc, uint2 u) {
    float2 f0 = __half22float2(*reinterpret_cast<__half2*>(&u.x));
    float2 f1 = __half22float2(*reinterpret_cast<__half2*>(&u.y));
    acc.x += f0.x; acc.y += f0.y; acc.z += f1.x; acc.w += f1.y;
}

// ---------------------------------------------------------------------------
// K3 (fused): conv1 gather (fp16, fp32 acc) -> relu -> max-pool-by-10
// -> write pooled features fp16 (NO projection here; W2 moved to k_final).
// Block = 32 clusters = 320 nodes; warp = 8 nodes x 4 lanes (lane = 4 feats, 8B).
__global__ void k_g1_pool() {
    __shared__ int pool_bits[32 * F1];   // pooled relu'd floats as bits
    int t = threadIdx.x;
    pool_bits[t] = 0;
    pool_bits[t + 256] = 0;
    __syncthreads();

    int wid = t >> 5, lane = t & 31;
    int q = lane & 3;
    int niw = lane >> 2;
    int nbase = blockIdx.x * 320;

#pragma unroll 1
    for (int pass = 0; pass < 5; pass++) {
        int n = nbase + pass * 64 + wid * 8 + niw;
        int d = g_cnt0[n]; if (d > MD0) d = MD0;
        int dmax = __reduce_max_sync(0xffffffffu, d);
        const int* __restrict__ cp = g_cols0 + (size_t)n * MD0;
        float4 acc = make_float4(0.f, 0.f, 0.f, 0.f);
        int cia = (q < d)     ? cp[q]     : N0;   // N0 = zero pad row
        int cib = (4 + q < d) ? cp[4 + q] : N0;
        for (int p0 = 0; p0 < dmax; p0 += 8) {
            int cna = (p0 + 8 + q < d)  ? cp[p0 + 8 + q]  : N0;
            int cnb = (p0 + 12 + q < d) ? cp[p0 + 12 + q] : N0;
            uint2 v[8];
#pragma unroll
            for (int i = 0; i < 4; i++) {
                int c = __shfl_sync(0xffffffffu, cia, i, 4);
                v[i] = *(reinterpret_cast<const uint2*>(g_xp1h + (size_t)c * F1) + q);
            }
#pragma unroll
            for (int i = 0; i < 4; i++) {
                int c = __shfl_sync(0xffffffffu, cib, i, 4);
                v[4 + i] = *(reinterpret_cast<const uint2*>(g_xp1h + (size_t)c * F1) + q);
            }
#pragma unroll
            for (int i = 0; i < 8; i++) acc_h4(acc, v[i]);
            cia = cna; cib = cnb;
        }
        // relu + pool (float-bit atomicMax valid: post-relu >= 0)
        int lc = (pass * 64 + wid * 8 + niw) / 10;
        int* pb = pool_bits + lc * F1 + q * 4;
        atomicMax(&pb[0], __float_as_int(fmaxf(acc.x, 0.f)));
        atomicMax(&pb[1], __float_as_int(fmaxf(acc.y, 0.f)));
        atomicMax(&pb[2], __float_as_int(fmaxf(acc.z, 0.f)));
        atomicMax(&pb[3], __float_as_int(fmaxf(acc.w, 0.f)));
    }
    __syncthreads();

    // write pooled features fp16: 512 values, thread t packs pair (2t, 2t+1)
    {
        __half2 h = __floats2half2_rn(__int_as_float(pool_bits[2 * t]),
                                      __int_as_float(pool_bits[2 * t + 1]));
        reinterpret_cast<__half2*>(g_xpoolh + (size_t)blockIdx.x * 32 * F1)[t] = h;
    }
}

// ---------------------------------------------------------------------------
// K4: conv2 gather on 16-dim pooled features (32B fp16 rows, table L1-resident).
// warp = 8 nodes x 4 lanes; lane = 4 feats (8B); fp32 acc; fp32 output (pre-W2).
__global__ void k_gather2(const int* __restrict__ ei1, int E1_) {
    int tid = blockIdx.x * blockDim.x + threadIdx.x;
    int gw = tid >> 5;
    int lane = threadIdx.x & 31;
    int q = lane & 3;
    int n = gw * 8 + (lane >> 2);
    int s = g_bnd[n];
    int d = g_bnd[NC0 + n] - s;
    int dmax = __reduce_max_sync(0xffffffffu, d);
    const int* __restrict__ colp = ei1 + E1_ + s;
    float4 acc = make_float4(0.f, 0.f, 0.f, 0.f);
    int cia = (q < d)     ? colp[q]     : NC0;   // NC0 = zero pad row
    int cib = (4 + q < d) ? colp[4 + q] : NC0;
    for (int p0 = 0; p0 < dmax; p0 += 8) {
        int cna = (p0 + 8 + q < d)  ? colp[p0 + 8 + q]  : NC0;
        int cnb = (p0 + 12 + q < d) ? colp[p0 + 12 + q] : NC0;
        uint2 v[8];
#pragma unroll
        for (int i = 0; i < 4; i++) {
            int c = __shfl_sync(0xffffffffu, cia, i, 4);
            v[i] = *(reinterpret_cast<const uint2*>(g_xpoolh + (size_t)c * F1) + q);
        }
#pragma unroll
        for (int i = 0; i < 4; i++) {
            int c = __shfl_sync(0xffffffffu, cib, i, 4);
            v[4 + i] = *(reinterpret_cast<const uint2*>(g_xpoolh + (size_t)c * F1) + q);
        }
#pragma unroll
        for (int i = 0; i < 8; i++) acc_h4(acc, v[i]);
        cia = cna; cib = cnb;
    }
    *reinterpret_cast<float4*>(g_s2 + (size_t)n * F1 + q * 4) = acc;
}

// ---------------------------------------------------------------------------
// K5: tail per graph: project s2@W2 -> relu -> max-by-10 -> mean-by-40
// -> fc1+relu -> fc2.  (projection before max, exactly as reference)
__global__ void k_final(const float* __restrict__ W2,
                        const float* __restrict__ fc1W, const float* __restrict__ fc1b,
                        const float* __restrict__ fc2W, const float* __restrict__ fc2b,
                        float* __restrict__ out) {
    int g = blockIdx.x;
    __shared__ float s2s[CPG * F1];   // 25.6 KB
    __shared__ float W2s[F1 * F2];    // 2 KB
    __shared__ float x3s[40 * F2];    // 5 KB
    __shared__ float xg[F2];
    __shared__ float h[64];
    for (int i = threadIdx.x; i < F1 * F2; i += 256) W2s[i] = W2[i];
    const float4* src = reinterpret_cast<const float4*>(g_s2 + (size_t)g * CPG * F1);
    float4* dst = reinterpret_cast<float4*>(s2s);
    for (int i = threadIdx.x; i < CPG * F1 / 4; i += 256) dst[i] = src[i];
    __syncthreads();

    // x3[c2][f] = max_{j<10} relu( s2[c2*10+j] . W2[:,f] )
    for (int idx = threadIdx.x; idx < 40 * F2; idx += 256) {
        int c2 = idx >> 5, f = idx & 31;
        float m = 0.f;   // relu folded into the max floor
#pragma unroll 2
        for (int j = 0; j < 10; j++) {
            const float* sr = s2s + (c2 * 10 + j) * F1;
            float acc = 0.f;
#pragma unroll
            for (int k = 0; k < F1; k++) acc = fmaf(sr[k], W2s[k * F2 + f], acc);
            m = fmaxf(m, acc);
        }
        x3s[idx] = m;
    }
    __syncthreads();
    if (threadIdx.x < F2) {
        float s = 0.f;
#pragma unroll
        for (int c2 = 0; c2 < 40; c2++) s += x3s[c2 * F2 + threadIdx.x];
        xg[threadIdx.x] = s * (1.f / 40.f);
    }
    __syncthreads();
    if (threadIdx.x < 64) {
        float acc = fc1b[threadIdx.x];
#pragma unroll
        for (int k = 0; k < F2; k++) acc = fmaf(xg[k], fc1W[k * 64 + threadIdx.x], acc);
        h[threadIdx.x] = fmaxf(acc, 0.f);
    }
    __syncthreads();
    if (threadIdx.x == 0) {
        float acc = fc2b[0];
#pragma unroll
        for (int j = 0; j < 64; j++) acc = fmaf(h[j], fc2W[j], acc);
        out[g] = acc;
    }
}

// ---------------------------------------------------------------------------
extern "C" void kernel_launch(void* const* d_in, const int* in_sizes, int n_in,
                              void* d_out, int out_size) {
    const float* x   = (const float*)d_in[0];
    const int*   ei  = (const int*)d_in[2];   // edge_index (2, E0) int32
    const int*   ei1 = (const int*)d_in[4];   // edge_index1 (2, E1) int32, sorted by row
    int E0 = in_sizes[2] / 2;
    int E1 = in_sizes[4] / 2;

    // Locate weight block by size signature
    int wb = -1;
    for (int i = 5; i + 9 < n_in; i++) {
        if (in_sizes[i] == FIN * F1 && in_sizes[i + 1] == 1 && in_sizes[i + 2] == 2 * F1 + 1 &&
            in_sizes[i + 3] == F1 * F2 && in_sizes[i + 5] == 2 * F2 + 1 &&
            in_sizes[i + 6] == F2 * 64 && in_sizes[i + 7] == 64 &&
            in_sizes[i + 8] == 64 && in_sizes[i + 9] == 1) {
            wb = i; break;
        }
    }
    if (wb < 0) wb = n_in - 10;
    const float* W1   = (const float*)d_in[wb + 0];
    const float* W2   = (const float*)d_in[wb + 3];
    const float* fc1W = (const float*)d_in[wb + 6];
    const float* fc1b = (const float*)d_in[wb + 7];
    const float* fc2W = (const float*)d_in[wb + 8];
    const float* fc2b = (const float*)d_in[wb + 9];

    k_proj1_init<<<PROJ_BLKS + (N0 + 255) / 256, 256>>>(x, W1);    // 0
    k_fill_bounds<<<(E0 + 255) / 256, 256>>>(ei, E0, ei1, E1);     // 1
    k_g1_pool<<<NC0 / 32, 256>>>();                                // 2 (800 blocks)
    k_gather2<<<NC0 * 4 / 256, 256>>>(ei1, E1);                    // 3 (400 blocks)
    k_final<<<NB, 256>>>(W2, fc1W, fc1b, fc2W, fc2b, (float*)d_out); // 4
}